// round 1
// baseline (speedup 1.0000x reference)
#include <cuda_runtime.h>
#include <math.h>

// Problem constants
#define Dm   2048
#define Bb   4
#define Tt   2048
#define Hh   32
#define HSm  64
#define MROWS (Bb*Tt)          // 8192
#define YSZ  (MROWS*Dm)        // 16777216

// ---------------- scratch (static device memory; no allocations) -------------
__device__ float g_xn  [YSZ];
__device__ float g_tmp [YSZ];
__device__ float g_k   [YSZ];
__device__ float g_v   [YSZ];
__device__ float g_u   [YSZ];   // stores u = 1 - sigmoid(z) directly
__device__ float g_r   [YSZ];
__device__ float g_outs[YSZ];

// ---------------- LayerNorm ---------------------------------------------------
// One block per row (8192 rows of 2048). 256 threads, 8 elems/thread.
__global__ __launch_bounds__(256) void ln_kernel(
    const float* __restrict__ x, const float* __restrict__ gam,
    const float* __restrict__ bet, float* __restrict__ out)
{
    __shared__ float red[18];
    const int row = blockIdx.x;
    const int t = threadIdx.x;
    const float* xr = x + (size_t)row * Dm;

    float4 a0 = *(const float4*)(xr + 4*t);
    float4 a1 = *(const float4*)(xr + 1024 + 4*t);
    float s  = a0.x+a0.y+a0.z+a0.w + a1.x+a1.y+a1.z+a1.w;
    float ss = a0.x*a0.x+a0.y*a0.y+a0.z*a0.z+a0.w*a0.w
             + a1.x*a1.x+a1.y*a1.y+a1.z*a1.z+a1.w*a1.w;
    #pragma unroll
    for (int o = 16; o; o >>= 1) {
        s  += __shfl_xor_sync(0xffffffffu, s,  o);
        ss += __shfl_xor_sync(0xffffffffu, ss, o);
    }
    if ((t & 31) == 0) { red[t>>5] = s; red[8 + (t>>5)] = ss; }
    __syncthreads();
    if (t == 0) {
        float S = 0.f, SS = 0.f;
        #pragma unroll
        for (int i = 0; i < 8; i++) { S += red[i]; SS += red[8+i]; }
        float mu  = S * (1.0f/Dm);
        float var = SS * (1.0f/Dm) - mu*mu;
        red[16] = mu;
        red[17] = rsqrtf(var + 1e-5f);
    }
    __syncthreads();
    const float mu = red[16], rstd = red[17];

    float4 g0 = *(const float4*)(gam + 4*t);
    float4 g1 = *(const float4*)(gam + 1024 + 4*t);
    float4 b0 = *(const float4*)(bet + 4*t);
    float4 b1 = *(const float4*)(bet + 1024 + 4*t);
    float* outr = out + (size_t)row * Dm;
    float4 r0, r1;
    r0.x = (a0.x - mu)*rstd*g0.x + b0.x;
    r0.y = (a0.y - mu)*rstd*g0.y + b0.y;
    r0.z = (a0.z - mu)*rstd*g0.z + b0.z;
    r0.w = (a0.w - mu)*rstd*g0.w + b0.w;
    r1.x = (a1.x - mu)*rstd*g1.x + b1.x;
    r1.y = (a1.y - mu)*rstd*g1.y + b1.y;
    r1.z = (a1.z - mu)*rstd*g1.z + b1.z;
    r1.w = (a1.w - mu)*rstd*g1.w + b1.w;
    *(float4*)(outr + 4*t)        = r0;
    *(float4*)(outr + 1024 + 4*t) = r1;
}

// ---------------- fp32 NT GEMM: C[m,n] = sum_k A[m,k] * W[n,k] ----------------
// 128x128x16 tiles, 256 threads, 8x8 micro-tile, double-buffered smem.
#define BM 128
#define BN 128
#define BK 16
#define PADm 4

#define EPI_NONE 0
#define EPI_SIG  1
#define EPI_USIG 2   // store 1 - sigmoid(acc + bias) = 1/(1+exp(acc+bias))

template<int EPI>
__global__ __launch_bounds__(256) void gemm_nt(
    const float* __restrict__ A, const float* __restrict__ W,
    const float* __restrict__ bias, float* __restrict__ C,
    int Kn, int Nn)
{
    __shared__ float As[2][BK][BM+PADm];
    __shared__ float Bs[2][BK][BN+PADm];

    const int t  = threadIdx.x;
    const int bm = blockIdx.y, bn = blockIdx.x;
    const int lrow = t >> 2;          // 0..63
    const int lk   = (t & 3) << 2;    // 0,4,8,12
    const int tm = t >> 4, tn = t & 15;

    const float* Ap = A + (size_t)(bm*BM + lrow) * Kn + lk;
    const float* Wp = W + (size_t)(bn*BN + lrow) * Kn + lk;

    float acc[8][8];
    #pragma unroll
    for (int i = 0; i < 8; i++)
        #pragma unroll
        for (int j = 0; j < 8; j++) acc[i][j] = 0.f;

    // prologue: tile 0
    float4 a0 = *(const float4*)(Ap);
    float4 a1 = *(const float4*)(Ap + (size_t)64*Kn);
    float4 b0 = *(const float4*)(Wp);
    float4 b1 = *(const float4*)(Wp + (size_t)64*Kn);
    As[0][lk+0][lrow] = a0.x; As[0][lk+1][lrow] = a0.y;
    As[0][lk+2][lrow] = a0.z; As[0][lk+3][lrow] = a0.w;
    As[0][lk+0][lrow+64] = a1.x; As[0][lk+1][lrow+64] = a1.y;
    As[0][lk+2][lrow+64] = a1.z; As[0][lk+3][lrow+64] = a1.w;
    Bs[0][lk+0][lrow] = b0.x; Bs[0][lk+1][lrow] = b0.y;
    Bs[0][lk+2][lrow] = b0.z; Bs[0][lk+3][lrow] = b0.w;
    Bs[0][lk+0][lrow+64] = b1.x; Bs[0][lk+1][lrow+64] = b1.y;
    Bs[0][lk+2][lrow+64] = b1.z; Bs[0][lk+3][lrow+64] = b1.w;
    __syncthreads();

    int buf = 0;
    for (int k0 = 0; k0 < Kn; k0 += BK) {
        const bool nx = (k0 + BK) < Kn;
        if (nx) {
            a0 = *(const float4*)(Ap + k0 + BK);
            a1 = *(const float4*)(Ap + k0 + BK + (size_t)64*Kn);
            b0 = *(const float4*)(Wp + k0 + BK);
            b1 = *(const float4*)(Wp + k0 + BK + (size_t)64*Kn);
        }
        #pragma unroll
        for (int kk = 0; kk < BK; kk++) {
            float4 af0 = *(const float4*)(&As[buf][kk][tm*8]);
            float4 af1 = *(const float4*)(&As[buf][kk][tm*8+4]);
            float4 bf0 = *(const float4*)(&Bs[buf][kk][tn*8]);
            float4 bf1 = *(const float4*)(&Bs[buf][kk][tn*8+4]);
            float av[8] = {af0.x,af0.y,af0.z,af0.w,af1.x,af1.y,af1.z,af1.w};
            float bv[8] = {bf0.x,bf0.y,bf0.z,bf0.w,bf1.x,bf1.y,bf1.z,bf1.w};
            #pragma unroll
            for (int i = 0; i < 8; i++)
                #pragma unroll
                for (int j = 0; j < 8; j++)
                    acc[i][j] = fmaf(av[i], bv[j], acc[i][j]);
        }
        if (nx) {
            int nb = buf ^ 1;
            As[nb][lk+0][lrow] = a0.x; As[nb][lk+1][lrow] = a0.y;
            As[nb][lk+2][lrow] = a0.z; As[nb][lk+3][lrow] = a0.w;
            As[nb][lk+0][lrow+64] = a1.x; As[nb][lk+1][lrow+64] = a1.y;
            As[nb][lk+2][lrow+64] = a1.z; As[nb][lk+3][lrow+64] = a1.w;
            Bs[nb][lk+0][lrow] = b0.x; Bs[nb][lk+1][lrow] = b0.y;
            Bs[nb][lk+2][lrow] = b0.z; Bs[nb][lk+3][lrow] = b0.w;
            Bs[nb][lk+0][lrow+64] = b1.x; Bs[nb][lk+1][lrow+64] = b1.y;
            Bs[nb][lk+2][lrow+64] = b1.z; Bs[nb][lk+3][lrow+64] = b1.w;
            __syncthreads();
            buf = nb;
        }
    }

    // epilogue
    float bvec[8];
    if (EPI == EPI_USIG) {
        #pragma unroll
        for (int j = 0; j < 8; j++) bvec[j] = bias[bn*BN + tn*8 + j];
    }
    float* Cp = C + (size_t)(bm*BM + tm*8) * Nn + bn*BN + tn*8;
    #pragma unroll
    for (int i = 0; i < 8; i++) {
        float outv[8];
        #pragma unroll
        for (int j = 0; j < 8; j++) {
            float v = acc[i][j];
            if (EPI == EPI_SIG)  v = 1.0f / (1.0f + expf(-v));
            if (EPI == EPI_USIG) v = 1.0f / (1.0f + expf(v + bvec[j]));
            outv[j] = v;
        }
        *(float4*)(Cp + (size_t)i*Nn)     = make_float4(outv[0],outv[1],outv[2],outv[3]);
        *(float4*)(Cp + (size_t)i*Nn + 4) = make_float4(outv[4],outv[5],outv[6],outv[7]);
    }
}

// ---------------- selective-WKV recurrent scan --------------------------------
// One block per (b,h). 256 threads, each owns a 4x4 tile of the 64x64 state.
// CH=8 steps are staged in smem per phase to amortize barriers.
#define CH 8
__global__ __launch_bounds__(256) void scan_kernel(
    const float* __restrict__ kA, const float* __restrict__ vA,
    const float* __restrict__ uA, const float* __restrict__ rA,
    const float* __restrict__ state0, float* __restrict__ outs,
    float* __restrict__ stateF)
{
    const int bh = blockIdx.x;            // 0..127
    const int b  = bh >> 5;
    const int h  = bh & 31;
    const size_t base = (size_t)b * Tt * Dm + (size_t)h * HSm;

    const int t  = threadIdx.x;
    const int ti = t >> 4;    // row group 0..15 (rows 4ti..4ti+3)
    const int tj = t & 15;    // col group 0..15 (cols 4tj..4tj+3)

    __shared__ float stg[4][CH][64];      // k, v, u, r
    __shared__ float pS[CH][16][64];      // partial sums over row groups

    float S[4][4];
    const float* st0 = state0 + (size_t)bh * 4096;
    #pragma unroll
    for (int ii = 0; ii < 4; ii++) {
        float4 s4 = *(const float4*)(st0 + (ti*4+ii)*64 + tj*4);
        S[ii][0]=s4.x; S[ii][1]=s4.y; S[ii][2]=s4.z; S[ii][3]=s4.w;
    }

    const float* bases[4] = { kA + base, vA + base, uA + base, rA + base };

    for (int c = 0; c < Tt/CH; c++) {
        const size_t coff = (size_t)c * CH * Dm;
        // stage CH steps of k/v/u/r (4 * CH * 64 floats)
        #pragma unroll
        for (int p = 0; p < (4*CH*64)/256; p++) {
            int g = t + p*256;
            int s = g >> 8;            // step within chunk
            int a = (g >> 6) & 3;      // which array
            int e = g & 63;            // element
            stg[a][s][e] = bases[a][coff + (size_t)s*Dm + e];
        }
        __syncthreads();

        #pragma unroll
        for (int s = 0; s < CH; s++) {
            float4 k4 = *(const float4*)(&stg[0][s][ti*4]);
            float4 v4 = *(const float4*)(&stg[1][s][tj*4]);
            float4 u4 = *(const float4*)(&stg[2][s][ti*4]);
            float4 r4 = *(const float4*)(&stg[3][s][ti*4]);
            float kv[4] = {k4.x,k4.y,k4.z,k4.w};
            float uv[4] = {u4.x,u4.y,u4.z,u4.w};
            float rv[4] = {r4.x,r4.y,r4.z,r4.w};
            float vv[4] = {v4.x,v4.y,v4.z,v4.w};
            float p0=0.f,p1=0.f,p2=0.f,p3=0.f;
            #pragma unroll
            for (int ii = 0; ii < 4; ii++) {
                S[ii][0] = fmaf(uv[ii], S[ii][0], kv[ii]*vv[0]);
                S[ii][1] = fmaf(uv[ii], S[ii][1], kv[ii]*vv[1]);
                S[ii][2] = fmaf(uv[ii], S[ii][2], kv[ii]*vv[2]);
                S[ii][3] = fmaf(uv[ii], S[ii][3], kv[ii]*vv[3]);
                p0 = fmaf(rv[ii], S[ii][0], p0);
                p1 = fmaf(rv[ii], S[ii][1], p1);
                p2 = fmaf(rv[ii], S[ii][2], p2);
                p3 = fmaf(rv[ii], S[ii][3], p3);
            }
            *(float4*)(&pS[s][ti][tj*4]) = make_float4(p0,p1,p2,p3);
        }
        __syncthreads();

        // reduce 16 row-group partials -> out, write CH*64 outputs
        float* op = outs + base + coff;
        #pragma unroll
        for (int q = 0; q < 2; q++) {
            int o = t + q*256;
            int s = o >> 6;
            int j = o & 63;
            float sum = 0.f;
            #pragma unroll
            for (int ii = 0; ii < 16; ii++) sum += pS[s][ii][j];
            op[(size_t)s*Dm + j] = sum;
        }
        __syncthreads();
    }

    // final state -> output tail region [B,H,HS,HS]
    float* sf = stateF + (size_t)bh * 4096;
    #pragma unroll
    for (int ii = 0; ii < 4; ii++)
        *(float4*)(sf + (ti*4+ii)*64 + tj*4)
            = make_float4(S[ii][0],S[ii][1],S[ii][2],S[ii][3]);
}

// ---------------- launch ------------------------------------------------------
extern "C" void kernel_launch(void* const* d_in, const int* in_sizes, int n_in,
                              void* d_out, int out_size)
{
    const float* x     = (const float*)d_in[0];
    const float* state = (const float*)d_in[1];
    const float* ln_g  = (const float*)d_in[2];
    const float* ln_b  = (const float*)d_in[3];
    const float* Wx    = (const float*)d_in[4];
    const float* Ww    = (const float*)d_in[5];
    const float* bw    = (const float*)d_in[6];
    const float* Wk    = (const float*)d_in[7];
    const float* Wv    = (const float*)d_in[8];
    const float* Wr    = (const float*)d_in[9];
    const float* Wo    = (const float*)d_in[10];

    float* y_out  = (float*)d_out;            // [B,T,D]
    float* sf_out = (float*)d_out + YSZ;      // [B,H,HS,HS]

    float *xn, *tmp, *kk, *vv, *uu, *rr, *oo;
    cudaGetSymbolAddress((void**)&xn,  g_xn);
    cudaGetSymbolAddress((void**)&tmp, g_tmp);
    cudaGetSymbolAddress((void**)&kk,  g_k);
    cudaGetSymbolAddress((void**)&vv,  g_v);
    cudaGetSymbolAddress((void**)&uu,  g_u);
    cudaGetSymbolAddress((void**)&rr,  g_r);
    cudaGetSymbolAddress((void**)&oo,  g_outs);

    // 1) LayerNorm
    ln_kernel<<<MROWS, 256>>>(x, ln_g, ln_b, xn);

    dim3 ggrid(Dm/BN, MROWS/BM);   // (16, 64)
    // 2) tmp = xn @ Wx^T
    gemm_nt<EPI_NONE><<<ggrid, 256>>>(xn, Wx, nullptr, tmp, Dm, Dm);
    // 3) u = 1 - sigmoid(tmp @ Ww^T + bw)
    gemm_nt<EPI_USIG><<<ggrid, 256>>>(tmp, Ww, bw, uu, Dm, Dm);
    // 4) k = xn @ Wk^T
    gemm_nt<EPI_NONE><<<ggrid, 256>>>(xn, Wk, nullptr, kk, Dm, Dm);
    // 5) v = xn @ Wv^T
    gemm_nt<EPI_NONE><<<ggrid, 256>>>(xn, Wv, nullptr, vv, Dm, Dm);
    // 6) r = sigmoid(xn @ Wr^T)
    gemm_nt<EPI_SIG><<<ggrid, 256>>>(xn, Wr, nullptr, rr, Dm, Dm);
    // 7) recurrent scan -> outs, final state
    scan_kernel<<<Bb*Hh, 256>>>(kk, vv, uu, rr, state, oo, sf_out);
    // 8) y = outs @ Wo^T
    gemm_nt<EPI_NONE><<<ggrid, 256>>>(oo, Wo, nullptr, y_out, Dm, Dm);
}